// round 12
// baseline (speedup 1.0000x reference)
#include <cuda_runtime.h>

#define Bn 8
#define Cn 64
#define Hn 64
#define Wn 64

typedef unsigned long long ull;

__device__ __forceinline__ ull pack2(float lo, float hi) {
    ull r; asm("mov.b64 %0, {%1, %2};" : "=l"(r) : "f"(lo), "f"(hi)); return r;
}
__device__ __forceinline__ void unpack2(ull v, float& lo, float& hi) {
    asm("mov.b64 {%0, %1}, %2;" : "=f"(lo), "=f"(hi) : "l"(v));
}
__device__ __forceinline__ ull ffma2(ull a, ull b, ull c) {
    ull d; asm("fma.rn.f32x2 %0, %1, %2, %3;" : "=l"(d) : "l"(a), "l"(b), "l"(c)); return d;
}
// (a.hi, b.lo)
__device__ __forceinline__ ull sp(ull a, ull b) {
    ull r;
    asm("{\n\t.reg .f32 al, ah, bl, bh;\n\t"
        "mov.b64 {al, ah}, %1;\n\t"
        "mov.b64 {bl, bh}, %2;\n\t"
        "mov.b64 %0, {ah, bl};\n\t}"
        : "=l"(r) : "l"(a), "l"(b));
    return r;
}
// (e, b.lo)
__device__ __forceinline__ ull spf(float e, ull b) {
    ull r;
    asm("{\n\t.reg .f32 bl, bh;\n\t"
        "mov.b64 {bl, bh}, %2;\n\t"
        "mov.b64 %0, {%1, bl};\n\t}"
        : "=l"(r) : "f"(e), "l"(b));
    return r;
}
// (a.hi, e)
__device__ __forceinline__ ull spl(ull a, float e) {
    ull r;
    asm("{\n\t.reg .f32 al, ah;\n\t"
        "mov.b64 {al, ah}, %1;\n\t"
        "mov.b64 %0, {ah, %2};\n\t}"
        : "=l"(r) : "l"(a), "f"(e));
    return r;
}

__device__ float g_f1[Bn*64*Hn*Wn];    // conv1 out [b][c][h][w]
__device__ float g_f2t[Bn*32*Wn*Hn];   // conv2 out transposed [b][c][w][h]

// 8-px row segment: 4 aligned pairs + 5 shifted pairs.
__device__ __forceinline__ void load_row8(ull* AP, ull* S, const float* rowp,
                                          int s8, bool nf, bool nl)
{
    const float* rp = rowp + s8;
    ulonglong2 q0 = *(const ulonglong2*)(rp);
    ulonglong2 q1 = *(const ulonglong2*)(rp + 4);
    AP[0]=q0.x; AP[1]=q0.y; AP[2]=q1.x; AP[3]=q1.y;
    float eL = nf ? rp[-1] : 0.f;
    float eR = nl ? rp[8]  : 0.f;
    S[0] = spf(eL, AP[0]);
    S[1] = sp(AP[0], AP[1]);
    S[2] = sp(AP[1], AP[2]);
    S[3] = sp(AP[2], AP[3]);
    S[4] = spl(AP[3], eR);
}

__device__ __forceinline__ void fma_row8(ull* acc, const ull* AP, const ull* S,
                                         ull W0, ull W1, ull W2)
{
#pragma unroll
    for (int p = 0; p < 4; p++) {
        acc[p] = ffma2(W0, S[p],   acc[p]);
        acc[p] = ffma2(W1, AP[p],  acc[p]);
        acc[p] = ffma2(W2, S[p+1], acc[p]);
    }
}

// ---------------------------------------------------------------------------
// conv1: 3x3 64->64, zero pad, bias+PReLU. lane = co (within half).
// Block 256 = 8 seg-warps of 8 px; 2 out rows. Per-row rolling: one AP/S
// buffer + rotating weight pairs -> ~65 regs, 3 CTAs/SM.
// Grid (32 rowpairs, 2 co-halves, 8 batch) = 512 blocks, 4096 warps.
// ---------------------------------------------------------------------------
__global__ __launch_bounds__(256, 3) void conv1_kernel(
    const float* __restrict__ x, const float* __restrict__ wgt,
    const float* __restrict__ bias, const float* __restrict__ alpha)
{
    const int h0  = blockIdx.x * 2;
    const int coH = blockIdx.y;
    const int b   = blockIdx.z;
    const int tid  = threadIdx.x;
    const int lane = tid & 31;          // co within half
    const int seg  = tid >> 5;          // 0..7
    const int s8   = seg * 8;
    const bool nf = (seg > 0), nl = (seg < 7);
    const int co = coH*32 + lane;

    __shared__ __align__(16) float sIn[8][4][64];   // [ci][rr][w], rr = h0-1+rr
    __shared__ float sWt[8][9][32];                 // this half's weights [ci][k][co]

    const int fw_co = tid & 31, fw_ci = tid >> 5;   // weight fill map

    ull acc0[4], acc1[4];
#pragma unroll
    for (int p = 0; p < 4; p++) { acc0[p] = 0ull; acc1[p] = 0ull; }

    for (int cb = 0; cb < 8; cb++) {
        // input fill: 512 float4, 2/thread
#pragma unroll
        for (int t = 0; t < 2; t++) {
            const int i  = tid + t*256;
            const int ci = i >> 6, rr = (i >> 4) & 3, c4 = i & 15;
            const int hh = h0 - 1 + rr;
            float4 v = make_float4(0.f, 0.f, 0.f, 0.f);
            if (hh >= 0 && hh < Hn)
                v = *(const float4*)&x[((b*64 + cb*8 + ci)*Hn + hh)*Wn + c4*4];
            *(float4*)&sIn[ci][rr][c4*4] = v;
        }
        {   // weight fill: thread = (co32, ci8), 9 k each
            const float* wp = wgt + ((coH*32 + fw_co)*64 + cb*8 + fw_ci)*9;
#pragma unroll
            for (int k = 0; k < 9; k++)
                sWt[fw_ci][k][fw_co] = wp[k];
        }
        __syncthreads();

#pragma unroll 2
        for (int ci = 0; ci < 8; ci++) {
            const float* wr = &sWt[ci][0][lane];
            ull AP[4], S[5];
            ull Wc0, Wc1, Wc2, Wp0, Wp1, Wp2;

            // rr=0: out0 <- ky0
            load_row8(AP, S, &sIn[ci][0][0], s8, nf, nl);
            { float a = wr[0], c = wr[32], e = wr[64];
              Wc0 = pack2(a,a); Wc1 = pack2(c,c); Wc2 = pack2(e,e); }
            fma_row8(acc0, AP, S, Wc0, Wc1, Wc2);

            // rr=1: out0 <- ky1, out1 <- ky0
            load_row8(AP, S, &sIn[ci][1][0], s8, nf, nl);
            Wp0 = Wc0; Wp1 = Wc1; Wp2 = Wc2;
            { float a = wr[96], c = wr[128], e = wr[160];
              Wc0 = pack2(a,a); Wc1 = pack2(c,c); Wc2 = pack2(e,e); }
            fma_row8(acc0, AP, S, Wc0, Wc1, Wc2);
            fma_row8(acc1, AP, S, Wp0, Wp1, Wp2);

            // rr=2: out0 <- ky2, out1 <- ky1
            load_row8(AP, S, &sIn[ci][2][0], s8, nf, nl);
            Wp0 = Wc0; Wp1 = Wc1; Wp2 = Wc2;
            { float a = wr[192], c = wr[224], e = wr[256];
              Wc0 = pack2(a,a); Wc1 = pack2(c,c); Wc2 = pack2(e,e); }
            fma_row8(acc0, AP, S, Wc0, Wc1, Wc2);
            fma_row8(acc1, AP, S, Wp0, Wp1, Wp2);

            // rr=3: out1 <- ky2
            load_row8(AP, S, &sIn[ci][3][0], s8, nf, nl);
            fma_row8(acc1, AP, S, Wc0, Wc1, Wc2);
        }
        __syncthreads();
    }

    const float bv = bias[co], av = alpha[co];
#pragma unroll
    for (int r = 0; r < 2; r++) {
        ull* ac = r ? acc1 : acc0;
        float o[8];
#pragma unroll
        for (int p = 0; p < 4; p++) unpack2(ac[p], o[2*p], o[2*p+1]);
#pragma unroll
        for (int e = 0; e < 8; e++) {
            float v = o[e] + bv;
            o[e] = v > 0.f ? v : av*v;
        }
        float* op = &g_f1[((b*64 + co)*Hn + h0 + r)*Wn + s8];
        *(float4*)op       = make_float4(o[0], o[1], o[2], o[3]);
        *(float4*)(op + 4) = make_float4(o[4], o[5], o[6], o[7]);
    }
}

// ---------------------------------------------------------------------------
// conv2: 3x3 64->32, zero pad, bias+PReLU, transposed out [b][c][w][h].
// Same template: lane = co (all 32), 8 seg-warps of 8 px, 2 out rows.
// Grid (32, 8) = 256 blocks, 2048 warps.
// ---------------------------------------------------------------------------
__global__ __launch_bounds__(256, 3) void conv2_kernel(
    const float* __restrict__ wgt, const float* __restrict__ bias,
    const float* __restrict__ alpha)
{
    const int h0 = blockIdx.x * 2;
    const int b  = blockIdx.y;
    const int tid  = threadIdx.x;
    const int lane = tid & 31;          // co
    const int seg  = tid >> 5;
    const int s8   = seg * 8;
    const bool nf = (seg > 0), nl = (seg < 7);

    __shared__ __align__(16) float sIn[8][4][64];
    __shared__ float sWt[8][9][32];

    const int fw_co = tid & 31, fw_ci = tid >> 5;

    ull acc0[4], acc1[4];
#pragma unroll
    for (int p = 0; p < 4; p++) { acc0[p] = 0ull; acc1[p] = 0ull; }

    for (int cb = 0; cb < 8; cb++) {
#pragma unroll
        for (int t = 0; t < 2; t++) {
            const int i  = tid + t*256;
            const int ci = i >> 6, rr = (i >> 4) & 3, c4 = i & 15;
            const int hh = h0 - 1 + rr;
            float4 v = make_float4(0.f, 0.f, 0.f, 0.f);
            if (hh >= 0 && hh < Hn)
                v = *(const float4*)&g_f1[((b*64 + cb*8 + ci)*Hn + hh)*Wn + c4*4];
            *(float4*)&sIn[ci][rr][c4*4] = v;
        }
        {
            const float* wp = wgt + (fw_co*64 + cb*8 + fw_ci)*9;
#pragma unroll
            for (int k = 0; k < 9; k++)
                sWt[fw_ci][k][fw_co] = wp[k];
        }
        __syncthreads();

#pragma unroll 2
        for (int ci = 0; ci < 8; ci++) {
            const float* wr = &sWt[ci][0][lane];
            ull AP[4], S[5];
            ull Wc0, Wc1, Wc2, Wp0, Wp1, Wp2;

            load_row8(AP, S, &sIn[ci][0][0], s8, nf, nl);
            { float a = wr[0], c = wr[32], e = wr[64];
              Wc0 = pack2(a,a); Wc1 = pack2(c,c); Wc2 = pack2(e,e); }
            fma_row8(acc0, AP, S, Wc0, Wc1, Wc2);

            load_row8(AP, S, &sIn[ci][1][0], s8, nf, nl);
            Wp0 = Wc0; Wp1 = Wc1; Wp2 = Wc2;
            { float a = wr[96], c = wr[128], e = wr[160];
              Wc0 = pack2(a,a); Wc1 = pack2(c,c); Wc2 = pack2(e,e); }
            fma_row8(acc0, AP, S, Wc0, Wc1, Wc2);
            fma_row8(acc1, AP, S, Wp0, Wp1, Wp2);

            load_row8(AP, S, &sIn[ci][2][0], s8, nf, nl);
            Wp0 = Wc0; Wp1 = Wc1; Wp2 = Wc2;
            { float a = wr[192], c = wr[224], e = wr[256];
              Wc0 = pack2(a,a); Wc1 = pack2(c,c); Wc2 = pack2(e,e); }
            fma_row8(acc0, AP, S, Wc0, Wc1, Wc2);
            fma_row8(acc1, AP, S, Wp0, Wp1, Wp2);

            load_row8(AP, S, &sIn[ci][3][0], s8, nf, nl);
            fma_row8(acc1, AP, S, Wc0, Wc1, Wc2);
        }
        __syncthreads();
    }

    const int co = lane;
    const float bv = bias[co], av = alpha[co];
#pragma unroll
    for (int r = 0; r < 2; r++) {
        ull* ac = r ? acc1 : acc0;
        const int h = h0 + r;
#pragma unroll
        for (int p = 0; p < 4; p++) {
            float lo, hi; unpack2(ac[p], lo, hi);
            lo += bv; hi += bv;
            lo = lo > 0.f ? lo : av*lo;
            hi = hi > 0.f ? hi : av*hi;
            const int w = s8 + 2*p;
            g_f2t[((b*32 + co)*Wn + w    )*Hn + h] = lo;
            g_f2t[((b*32 + co)*Wn + w + 1)*Hn + h] = hi;
        }
    }
}

// ---------------------------------------------------------------------------
// Fused: 1x1 conv (K=32) + softmax(9) + upsample. 128 thr, 8192 blocks.
// (unchanged from round 11)
// ---------------------------------------------------------------------------
__global__ __launch_bounds__(128, 4) void fused_kernel(
    const float* __restrict__ xlow, const float* __restrict__ kw,
    const float* __restrict__ kb, float* __restrict__ out)
{
    const int cchunk = blockIdx.x;
    const int w      = blockIdx.y;
    const int b      = blockIdx.z;
    const int tid = threadIdx.x;
    const int pg  = tid & 7;
    const int pq  = (tid >> 3) & 3;
    const int c_l = tid >> 5;

    __shared__ float swt[144*33];                  // plain f32 weights, pad 33
    __shared__ __align__(16) float sf2[32*64];     // [ci][h]
    __shared__ __align__(16) float sx[4][3][68];   // edge-clamped x_low patch
    __shared__ float sbias[144];

    for (int idx = tid; idx < 32*64; idx += 128)
        sf2[idx] = g_f2t[((b*32 + (idx >> 6))*Wn + w)*Hn + (idx & 63)];
    for (int idx = tid; idx < 144*32; idx += 128) {
        int r = idx >> 5, ci = idx & 31;
        swt[r*33 + ci] = kw[(cchunk*144 + r)*32 + ci];
    }
    for (int idx = tid; idx < 144; idx += 128) sbias[idx] = kb[cchunk*144 + idx];
    for (int idx = tid; idx < 4*3*66; idx += 128) {
        int cl = idx / 198;
        int dx = (idx % 198) / 66;
        int hh = idx % 66;
        int hr = min(max(hh - 1, 0), Hn - 1);
        int wc = min(max(w + dx - 1, 0), Wn - 1);
        sx[cl][dx][hh] = xlow[((b*Cn + cchunk*4 + cl)*Hn + hr)*Wn + wc];
    }
    __syncthreads();

    ull m[9][4];
#pragma unroll
    for (int k = 0; k < 9; k++)
#pragma unroll
        for (int j = 0; j < 4; j++) m[k][j] = 0ull;

    const int rowb = c_l*36 + pq;
    const float* wtb = &swt[rowb*33];

#pragma unroll 4
    for (int ci = 0; ci < 32; ci++) {
        ulonglong2 p01 = *(const ulonglong2*)&sf2[ci*64 + pg*8];
        ulonglong2 p23 = *(const ulonglong2*)&sf2[ci*64 + pg*8 + 4];
        ull P[4] = {p01.x, p01.y, p23.x, p23.y};
        ull W[9];
#pragma unroll
        for (int k = 0; k < 9; k++) {
            float v = wtb[k*132 + ci];   // 132 = 4*33 (rows step by 4)
            W[k] = pack2(v, v);
        }
#pragma unroll
        for (int k = 0; k < 9; k++)
#pragma unroll
            for (int j = 0; j < 4; j++) m[k][j] = ffma2(W[k], P[j], m[k][j]);
    }

    float b9[9];
#pragma unroll
    for (int k = 0; k < 9; k++) b9[k] = sbias[rowb + k*4];

    float nbd[3][10];
#pragma unroll
    for (int dx = 0; dx < 3; dx++) {
        float4 q0 = *(const float4*)&sx[c_l][dx][pg*8];
        float4 q1 = *(const float4*)&sx[c_l][dx][pg*8 + 4];
        float2 q2 = *(const float2*)&sx[c_l][dx][pg*8 + 8];
        nbd[dx][0]=q0.x; nbd[dx][1]=q0.y; nbd[dx][2]=q0.z; nbd[dx][3]=q0.w;
        nbd[dx][4]=q1.x; nbd[dx][5]=q1.y; nbd[dx][6]=q1.z; nbd[dx][7]=q1.w;
        nbd[dx][8]=q2.x; nbd[dx][9]=q2.y;
    }

    const int c = cchunk*4 + c_l;
    const int p = pq >> 1, q = pq & 1;
    float* orow = &out[((b*Cn + c)*128 + (2*w + q))*128 + p];

#pragma unroll
    for (int jj = 0; jj < 4; jj++) {
        float lo[9], hi[9];
#pragma unroll
        for (int k = 0; k < 9; k++) unpack2(m[k][jj], lo[k], hi[k]);
#pragma unroll
        for (int e = 0; e < 2; e++) {
            const int j = 2*jj + e;
            const float* lv = e ? hi : lo;
            float se = 0.f, sv = 0.f;
#pragma unroll
            for (int k = 0; k < 9; k++) {
                float ex = __expf(lv[k] + b9[k]);   // logits tiny: no max-sub needed
                se += ex;
                sv = fmaf(ex, nbd[k % 3][j + k / 3], sv);
            }
            orow[2*(pg*8 + j)] = sv * __fdividef(1.f, se);
        }
    }
}

extern "C" void kernel_launch(void* const* d_in, const int* in_sizes, int n_in,
                              void* d_out, int out_size)
{
    const float* x_low = (const float*)d_in[0];
    const float* ctx   = (const float*)d_in[1];
    const float* c1_w  = (const float*)d_in[2];
    const float* c1_b  = (const float*)d_in[3];
    const float* p1_a  = (const float*)d_in[4];
    const float* c2_w  = (const float*)d_in[5];
    const float* c2_b  = (const float*)d_in[6];
    const float* p2_a  = (const float*)d_in[7];
    const float* kp_w  = (const float*)d_in[8];
    const float* kp_b  = (const float*)d_in[9];
    float* out = (float*)d_out;

    conv1_kernel<<<dim3(32, 2, 8), 256>>>(ctx, c1_w, c1_b, p1_a);
    conv2_kernel<<<dim3(32, 8), 256>>>(c2_w, c2_b, p2_a);
    fused_kernel<<<dim3(16, Wn, Bn), 128>>>(x_low, kp_w, kp_b, out);
}